// round 2
// baseline (speedup 1.0000x reference)
#include <cuda_runtime.h>
#include <cstdint>

#define N_NODES  100000
#define N_EDGES  1600000
#define N_GRAPHS 512
#define DH 128
#define DL 64
#define N_LAYERS 3
#define BN_EPS 1e-5f

// ---------------- scratch (static __device__ globals: allocation-free) -------
__device__ int   g_cnt[N_NODES];
__device__ int   g_off[N_NODES + 1];
__device__ int   g_cur[N_NODES];
__device__ int   g_csr[N_EDGES];
__device__ float g_h0[N_NODES * DH];
__device__ float g_t [N_NODES * DH];
__device__ float g_xa[N_NODES * DH];
__device__ float g_xb[N_NODES * DH];
__device__ float g_sum[DH], g_sq[DH], g_scale[DH], g_shift[DH];
__device__ float g_pool[N_GRAPHS * DH];
__device__ int   g_gstart[N_GRAPHS + 1];
__device__ float g_f1[N_GRAPHS * DL];
__device__ float g_fsum[DL], g_fsq[DL], g_fscale[DL], g_fshift[DL];

// ---------------- f32x2 helpers (Blackwell packed fp32) ----------------------
__device__ __forceinline__ unsigned long long pack2(float lo, float hi) {
    unsigned long long r;
    asm("mov.b64 %0, {%1, %2};" : "=l"(r) : "f"(lo), "f"(hi));
    return r;
}
__device__ __forceinline__ unsigned long long fma2(unsigned long long a,
                                                   unsigned long long b,
                                                   unsigned long long c) {
    unsigned long long d;
    asm("fma.rn.f32x2 %0, %1, %2, %3;" : "=l"(d) : "l"(a), "l"(b), "l"(c));
    return d;
}
__device__ __forceinline__ float2 unpack2(unsigned long long v) {
    float2 f;
    asm("mov.b64 {%0, %1}, %2;" : "=f"(f.x), "=f"(f.y) : "l"(v));
    return f;
}

__device__ __forceinline__ float leaky(float x) { return x > 0.f ? x : 0.2f * x; }

// ---------------- CSR build --------------------------------------------------
__global__ void k_zero_cnt() {
    int i = blockIdx.x * blockDim.x + threadIdx.x;
    if (i < N_NODES) g_cnt[i] = 0;
}

__global__ void k_hist(const int* __restrict__ ei) {
    int e = blockIdx.x * blockDim.x + threadIdx.x;
    if (e < N_EDGES) atomicAdd(&g_cnt[ei[N_EDGES + e]], 1);
}

// single-block exclusive scan of g_cnt -> g_off (and g_cur copy)
__global__ void k_scan() {
    __shared__ int ss[1024];
    const int tid = threadIdx.x;
    const int CH = (N_NODES + 1023) / 1024;   // 98 per thread
    int base = tid * CH;
    int s = 0;
    for (int i = 0; i < CH; i++) {
        int idx = base + i;
        if (idx < N_NODES) s += g_cnt[idx];
    }
    ss[tid] = s;
    __syncthreads();
    for (int o = 1; o < 1024; o <<= 1) {
        int v = (tid >= o) ? ss[tid - o] : 0;
        __syncthreads();
        ss[tid] += v;
        __syncthreads();
    }
    int run = ss[tid] - s;   // exclusive prefix of this thread's chunk
    for (int i = 0; i < CH; i++) {
        int idx = base + i;
        if (idx < N_NODES) {
            g_off[idx] = run;
            g_cur[idx] = run;
            run += g_cnt[idx];
        }
    }
    if (tid == 1023) g_off[N_NODES] = ss[1023];
}

__global__ void k_fill(const int* __restrict__ ei) {
    int e = blockIdx.x * blockDim.x + threadIdx.x;
    if (e < N_EDGES) {
        int s = ei[e];
        int d = ei[N_EDGES + e];
        int p = atomicAdd(&g_cur[d], 1);
        g_csr[p] = s;
    }
}

// ---------------- aggregation: h0 = x + sum_{src in N(dst)} x[src] ----------
// warp per node, float4 per lane (128 floats/row = 512B coalesced)
__global__ __launch_bounds__(256) void k_agg(const float* __restrict__ x) {
    int node = (blockIdx.x * 256 + threadIdx.x) >> 5;
    int lane = threadIdx.x & 31;
    if (node >= N_NODES) return;
    int e0 = g_off[node], e1 = g_off[node + 1];
    const float4* xv = (const float4*)x;
    float4 acc = xv[node * 32 + lane];
    int e = e0;
    for (; e + 1 < e1; e += 2) {
        int a = g_csr[e], b = g_csr[e + 1];
        float4 va = xv[a * 32 + lane];
        float4 vb = xv[b * 32 + lane];
        acc.x += va.x + vb.x; acc.y += va.y + vb.y;
        acc.z += va.z + vb.z; acc.w += va.w + vb.w;
    }
    if (e < e1) {
        float4 va = xv[g_csr[e] * 32 + lane];
        acc.x += va.x; acc.y += va.y; acc.z += va.z; acc.w += va.w;
    }
    ((float4*)g_h0)[node * 32 + lane] = acc;
}

// ---------------- GEMM: out = leaky( (optional BN(A)) @ W + b ) -------------
// BM=64 rows/block, 256 threads = 16x16, thread tile 4 rows x 8 cols
// (cols = tx + 16*j), f32x2 packed accumulators -> 2 FMA/instruction.
#define GEMM_SMEM_BYTES ((64 * 129 + 128 * 128) * 4)

template <bool PRE_BN>
__global__ __launch_bounds__(256) void k_gemm(const float* __restrict__ A,
                                              const float* __restrict__ W,
                                              const float* __restrict__ bias,
                                              float* __restrict__ out, int M) {
    extern __shared__ float sm[];
    float* sA = sm;                 // [64][129] padded: conflict-free column reads
    float* sW = sm + 64 * 129;      // [128][128]
    const int tid = threadIdx.x;
    const int bm = blockIdx.x;

#pragma unroll
    for (int i = 0; i < 64; i++) sW[i * 256 + tid] = W[i * 256 + tid];

#pragma unroll
    for (int i = 0; i < 32; i++) {
        int idx = i * 256 + tid;
        int r = idx >> 7, k = idx & 127;
        int row = bm * 64 + r;
        float v = (row < M) ? A[row * DH + k] : 0.f;
        if (PRE_BN) v = v * g_scale[k] + g_shift[k];
        sA[r * 129 + k] = v;
    }
    __syncthreads();

    const int tx = tid & 15, ty = tid >> 4;
    unsigned long long acc[4][4];
#pragma unroll
    for (int i = 0; i < 4; i++)
#pragma unroll
        for (int p = 0; p < 4; p++) acc[i][p] = 0ull;

#pragma unroll 4
    for (int k = 0; k < 128; k++) {
        unsigned long long aa[4];
#pragma unroll
        for (int i = 0; i < 4; i++) {
            float a = sA[(ty * 4 + i) * 129 + k];
            aa[i] = pack2(a, a);
        }
        unsigned long long bb[4];
#pragma unroll
        for (int p = 0; p < 4; p++) {
            float b0 = sW[k * 128 + tx + 32 * p];
            float b1 = sW[k * 128 + tx + 32 * p + 16];
            bb[p] = pack2(b0, b1);
        }
#pragma unroll
        for (int i = 0; i < 4; i++)
#pragma unroll
            for (int p = 0; p < 4; p++) acc[i][p] = fma2(aa[i], bb[p], acc[i][p]);
    }

    float bs0[4], bs1[4];
#pragma unroll
    for (int p = 0; p < 4; p++) {
        bs0[p] = bias[tx + 32 * p];
        bs1[p] = bias[tx + 32 * p + 16];
    }
#pragma unroll
    for (int i = 0; i < 4; i++) {
        int row = bm * 64 + ty * 4 + i;
        if (row >= M) continue;
#pragma unroll
        for (int p = 0; p < 4; p++) {
            float2 v = unpack2(acc[i][p]);
            out[row * DH + tx + 32 * p]      = leaky(v.x + bs0[p]);
            out[row * DH + tx + 32 * p + 16] = leaky(v.y + bs1[p]);
        }
    }
}

// ---------------- BN statistics over columns --------------------------------
__global__ void k_zero_stats() {
    int c = threadIdx.x;
    if (c < DH) g_sum[c] = 0.f;
    else if (c < 2 * DH) g_sq[c - DH] = 0.f;
}

__global__ __launch_bounds__(128) void k_colstats(const float* __restrict__ t, int M) {
    int c = threadIdx.x;
    int r0 = blockIdx.x * 512;
    int r1 = min(r0 + 512, M);
    float s = 0.f, q = 0.f;
    for (int r = r0; r < r1; r++) {
        float v = t[r * DH + c];
        s += v; q += v * v;
    }
    atomicAdd(&g_sum[c], s);
    atomicAdd(&g_sq[c], q);
}

__global__ void k_finalize(const float* __restrict__ gam, const float* __restrict__ bet,
                           float invM) {
    int c = threadIdx.x;
    float mean = g_sum[c] * invM;
    float var = g_sq[c] * invM - mean * mean;
    float rstd = rsqrtf(var + BN_EPS);
    float sc = gam[c] * rstd;
    g_scale[c] = sc;
    g_shift[c] = bet[c] - mean * sc;
}

// ---------------- pooling ----------------------------------------------------
__global__ void k_gstart_init() {
    int i = threadIdx.x + blockIdx.x * blockDim.x;
    if (i <= N_GRAPHS) g_gstart[i] = N_NODES;
}
__global__ void k_gstart_mark(const int* __restrict__ batch) {
    int i = blockIdx.x * blockDim.x + threadIdx.x;
    if (i < N_NODES) {
        if (i == 0 || batch[i] != batch[i - 1]) g_gstart[batch[i]] = i;
    }
}
__global__ void k_gstart_fix() {
    for (int g = N_GRAPHS - 1; g >= 0; g--)
        if (g_gstart[g] == N_NODES) g_gstart[g] = g_gstart[g + 1];
}
__global__ __launch_bounds__(128) void k_pool(const float* __restrict__ x) {
    int g = blockIdx.x, c = threadIdx.x;
    int r0 = g_gstart[g], r1 = g_gstart[g + 1];
    float s = 0.f;
    for (int r = r0; r < r1; r++) s += x[r * DH + c];
    g_pool[g * DH + c] = s;
}

// ---------------- head -------------------------------------------------------
__global__ __launch_bounds__(128) void k_pool_stats(const float* __restrict__ bn_g,
                                                    const float* __restrict__ bn_b) {
    int c = threadIdx.x;
    float s = 0.f, q = 0.f;
    for (int g = 0; g < N_GRAPHS; g++) {
        float v = g_pool[g * DH + c];
        s += v; q += v * v;
    }
    float mean = s / (float)N_GRAPHS;
    float var = q / (float)N_GRAPHS - mean * mean;
    float rstd = rsqrtf(var + BN_EPS);
    float sc = bn_g[c] * rstd;
    g_scale[c] = sc;
    g_shift[c] = bn_b[c] - mean * sc;
    if (c < DL) { g_fsum[c] = 0.f; g_fsq[c] = 0.f; }
}

__global__ __launch_bounds__(64) void k_head2(const float* __restrict__ feats,
                                              const float* __restrict__ fcW,
                                              const float* __restrict__ fcb,
                                              const float* __restrict__ cW1,
                                              const float* __restrict__ cb1,
                                              const float* __restrict__ cW2,
                                              const float* __restrict__ cb2,
                                              const float* __restrict__ fW1,
                                              const float* __restrict__ fb1) {
    __shared__ float cat[DL + 8];
    __shared__ float t8[8];
    int g = blockIdx.x, j = threadIdx.x;
    if (j < 8) {
        float s = cb1[j];
        for (int i = 0; i < 7; i++) s += feats[g * 7 + i] * cW1[i * 8 + j];
        t8[j] = fmaxf(s, 0.f);
    }
    __syncthreads();
    if (j < 8) {
        float s = cb2[j];
        for (int i = 0; i < 8; i++) s += t8[i] * cW2[i * 8 + j];
        cat[DL + j] = s;
    }
    float o = fcb[j];
    for (int k = 0; k < DH; k++) {
        float a = g_pool[g * DH + k] * g_scale[k] + g_shift[k];
        o += a * fcW[k * DL + j];
    }
    cat[j] = o;
    __syncthreads();
    float s = fb1[j];
    for (int k = 0; k < DL + 8; k++) s += cat[k] * fW1[k * DL + j];
    float v = leaky(s);
    g_f1[g * DL + j] = v;
    atomicAdd(&g_fsum[j], v);
    atomicAdd(&g_fsq[j], v * v);
}

__global__ __launch_bounds__(64) void k_head3(const float* __restrict__ f_g,
                                              const float* __restrict__ f_b) {
    int j = threadIdx.x;
    float mean = g_fsum[j] / (float)N_GRAPHS;
    float var = g_fsq[j] / (float)N_GRAPHS - mean * mean;
    float rstd = rsqrtf(var + BN_EPS);
    float sc = f_g[j] * rstd;
    g_fscale[j] = sc;
    g_fshift[j] = f_b[j] - mean * sc;
}

__global__ __launch_bounds__(64) void k_head4(const float* __restrict__ fW2,
                                              const float* __restrict__ fb2,
                                              float* __restrict__ out) {
    int g = blockIdx.x, j = threadIdx.x;
    float s = fb2[j];
    for (int k = 0; k < DL; k++) {
        float a = g_f1[g * DL + k] * g_fscale[k] + g_fshift[k];
        s += a * fW2[k * DL + j];
    }
    out[g * DL + j] = s;
}

// ---------------- launch -----------------------------------------------------
extern "C" void kernel_launch(void* const* d_in, const int* in_sizes, int n_in,
                              void* d_out, int out_size) {
    (void)in_sizes; (void)n_in; (void)out_size;
    const float* x      = (const float*)d_in[0];
    const int*   ei     = (const int*)  d_in[1];
    const int*   batch  = (const int*)  d_in[2];
    const float* feats  = (const float*)d_in[3];
    const float* convW1 = (const float*)d_in[4];
    const float* convb1 = (const float*)d_in[5];
    const float* convg1 = (const float*)d_in[6];
    const float* convbb1= (const float*)d_in[7];
    const float* convW2 = (const float*)d_in[8];
    const float* convb2 = (const float*)d_in[9];
    const float* bn_g   = (const float*)d_in[10];
    const float* bn_b   = (const float*)d_in[11];
    const float* fcW    = (const float*)d_in[12];
    const float* fcb    = (const float*)d_in[13];
    const float* cW1    = (const float*)d_in[14];
    const float* cb1    = (const float*)d_in[15];
    const float* cW2    = (const float*)d_in[16];
    const float* cb2    = (const float*)d_in[17];
    const float* fW1    = (const float*)d_in[18];
    const float* fb1    = (const float*)d_in[19];
    const float* f_g    = (const float*)d_in[20];
    const float* f_b    = (const float*)d_in[21];
    const float* fW2    = (const float*)d_in[22];
    const float* fb2    = (const float*)d_in[23];
    float* out = (float*)d_out;

    static bool attr_done = false;
    if (!attr_done) {
        cudaFuncSetAttribute(k_gemm<false>, cudaFuncAttributeMaxDynamicSharedMemorySize,
                             GEMM_SMEM_BYTES);
        cudaFuncSetAttribute(k_gemm<true>, cudaFuncAttributeMaxDynamicSharedMemorySize,
                             GEMM_SMEM_BYTES);
        attr_done = true;
    }

    float *dxa, *dxb, *dh0, *dt;
    cudaGetSymbolAddress((void**)&dxa, g_xa);
    cudaGetSymbolAddress((void**)&dxb, g_xb);
    cudaGetSymbolAddress((void**)&dh0, g_h0);
    cudaGetSymbolAddress((void**)&dt,  g_t);

    // CSR build (rebuilt every launch: deterministic same-work)
    k_zero_cnt<<<(N_NODES + 255) / 256, 256>>>();
    k_hist<<<(N_EDGES + 255) / 256, 256>>>(ei);
    k_scan<<<1, 1024>>>();
    k_fill<<<(N_EDGES + 255) / 256, 256>>>(ei);

    const int AGG_GRID  = (N_NODES * 32 + 255) / 256;
    const int GEMM_GRID = (N_NODES + 63) / 64;
    const int STAT_GRID = (N_NODES + 511) / 512;
    const float invM = 1.0f / (float)N_NODES;

    float* xouts[3] = {dxa, dxb, dxa};
    const float* xin = x;

    for (int l = 0; l < N_LAYERS; l++) {
        k_agg<<<AGG_GRID, 256>>>(xin);
        k_gemm<false><<<GEMM_GRID, 256, GEMM_SMEM_BYTES>>>(
            dh0, convW1 + l * DH * DH, convb1 + l * DH, dt, N_NODES);
        k_zero_stats<<<1, 256>>>();
        k_colstats<<<STAT_GRID, 128>>>(dt, N_NODES);
        k_finalize<<<1, 128>>>(convg1 + l * DH, convbb1 + l * DH, invM);
        k_gemm<true><<<GEMM_GRID, 256, GEMM_SMEM_BYTES>>>(
            dt, convW2 + l * DH * DH, convb2 + l * DH, xouts[l], N_NODES);
        xin = xouts[l];
    }

    // pooling via sorted-batch ranges (atomic-free)
    k_gstart_init<<<3, 256>>>();
    k_gstart_mark<<<(N_NODES + 255) / 256, 256>>>(batch);
    k_gstart_fix<<<1, 1>>>();
    k_pool<<<N_GRAPHS, 128>>>(xin);

    // head
    k_pool_stats<<<1, 128>>>(bn_g, bn_b);
    k_head2<<<N_GRAPHS, 64>>>(feats, fcW, fcb, cW1, cb1, cW2, cb2, fW1, fb1);
    k_head3<<<1, 64>>>(f_g, f_b);
    k_head4<<<N_GRAPHS, 64>>>(fW2, fb2, out);
}

// round 3
// speedup vs baseline: 1.0301x; 1.0301x over previous
#include <cuda_runtime.h>
#include <cstdint>

#define N_NODES  100000
#define N_EDGES  1600000
#define N_GRAPHS 512
#define DH 128
#define DL 64
#define N_LAYERS 3
#define BN_EPS 1e-5f

// ---------------- scratch (static __device__ globals: allocation-free) -------
__device__ int   g_cnt[N_NODES];
__device__ int   g_off[N_NODES + 1];
__device__ int   g_cur[N_NODES];
__device__ int   g_csr[N_EDGES];
__device__ float g_h0[N_NODES * DH];
__device__ float g_t [N_NODES * DH];
__device__ float g_xa[N_NODES * DH];
__device__ float g_xb[N_NODES * DH];
__device__ float g_sum[N_LAYERS * DH], g_sq[N_LAYERS * DH];
__device__ float g_scale[DH], g_shift[DH];
__device__ float g_pool[N_GRAPHS * DH];
__device__ int   g_gstart[N_GRAPHS + 1];
__device__ float g_f1[N_GRAPHS * DL];
__device__ float g_fsum[DL], g_fsq[DL], g_fscale[DL], g_fshift[DL];

// ---------------- f32x2 helpers (Blackwell packed fp32) ----------------------
__device__ __forceinline__ unsigned long long pack2(float lo, float hi) {
    unsigned long long r;
    asm("mov.b64 %0, {%1, %2};" : "=l"(r) : "f"(lo), "f"(hi));
    return r;
}
__device__ __forceinline__ unsigned long long fma2(unsigned long long a,
                                                   unsigned long long b,
                                                   unsigned long long c) {
    unsigned long long d;
    asm("fma.rn.f32x2 %0, %1, %2, %3;" : "=l"(d) : "l"(a), "l"(b), "l"(c));
    return d;
}
__device__ __forceinline__ float2 unpack2(unsigned long long v) {
    float2 f;
    asm("mov.b64 {%0, %1}, %2;" : "=f"(f.x), "=f"(f.y) : "l"(v));
    return f;
}

__device__ __forceinline__ float leaky(float x) { return x > 0.f ? x : 0.2f * x; }

// ---------------- CSR build --------------------------------------------------
__global__ void k_zero_cnt() {
    int i = blockIdx.x * blockDim.x + threadIdx.x;
    if (i < N_NODES) g_cnt[i] = 0;
    if (i < N_LAYERS * DH) { g_sum[i] = 0.f; g_sq[i] = 0.f; }
}

__global__ void k_hist(const int* __restrict__ ei) {
    int e = blockIdx.x * blockDim.x + threadIdx.x;
    if (e < N_EDGES) atomicAdd(&g_cnt[ei[N_EDGES + e]], 1);
}

// single-block exclusive scan of g_cnt -> g_off (and g_cur copy)
__global__ void k_scan() {
    __shared__ int ss[1024];
    const int tid = threadIdx.x;
    const int CH = (N_NODES + 1023) / 1024;   // 98 per thread
    int base = tid * CH;
    int s = 0;
    for (int i = 0; i < CH; i++) {
        int idx = base + i;
        if (idx < N_NODES) s += g_cnt[idx];
    }
    ss[tid] = s;
    __syncthreads();
    for (int o = 1; o < 1024; o <<= 1) {
        int v = (tid >= o) ? ss[tid - o] : 0;
        __syncthreads();
        ss[tid] += v;
        __syncthreads();
    }
    int run = ss[tid] - s;   // exclusive prefix of this thread's chunk
    for (int i = 0; i < CH; i++) {
        int idx = base + i;
        if (idx < N_NODES) {
            g_off[idx] = run;
            g_cur[idx] = run;
            run += g_cnt[idx];
        }
    }
    if (tid == 1023) g_off[N_NODES] = ss[1023];
}

__global__ void k_fill(const int* __restrict__ ei) {
    int e = blockIdx.x * blockDim.x + threadIdx.x;
    if (e < N_EDGES) {
        int s = ei[e];
        int d = ei[N_EDGES + e];
        int p = atomicAdd(&g_cur[d], 1);
        g_csr[p] = s;
    }
}

// ---------------- aggregation: h0 = x + sum_{src in N(dst)} x[src] ----------
// warp per node, float4 per lane (128 floats/row = 512B coalesced), unroll 4
__global__ __launch_bounds__(256) void k_agg(const float* __restrict__ x) {
    int node = (blockIdx.x * 256 + threadIdx.x) >> 5;
    int lane = threadIdx.x & 31;
    if (node >= N_NODES) return;
    int e0 = g_off[node], e1 = g_off[node + 1];
    const float4* xv = (const float4*)x;
    float4 acc = xv[node * 32 + lane];
    int e = e0;
    for (; e + 3 < e1; e += 4) {
        int a = g_csr[e], b = g_csr[e + 1], c = g_csr[e + 2], d = g_csr[e + 3];
        float4 va = xv[a * 32 + lane];
        float4 vb = xv[b * 32 + lane];
        float4 vc = xv[c * 32 + lane];
        float4 vd = xv[d * 32 + lane];
        acc.x += (va.x + vb.x) + (vc.x + vd.x);
        acc.y += (va.y + vb.y) + (vc.y + vd.y);
        acc.z += (va.z + vb.z) + (vc.z + vd.z);
        acc.w += (va.w + vb.w) + (vc.w + vd.w);
    }
    for (; e < e1; e++) {
        float4 va = xv[g_csr[e] * 32 + lane];
        acc.x += va.x; acc.y += va.y; acc.z += va.z; acc.w += va.w;
    }
    ((float4*)g_h0)[node * 32 + lane] = acc;
}

// ---------------- GEMM: out = leaky( (optional BN(A)) @ W + b ) -------------
// BM=128 rows/block, 512 threads = 16(tx) x 32(ty), thread tile 4 rows x 8 cols.
// Cols are 4 ADJACENT pairs (c0 = 2*tx + 32*p): B operand loads as LDS.64 with
// no packing mov; A is scalar-broadcast packed. 28 issue slots / 32 FMA per k.
// Optional fused epilogue: column sum/sumsq (BatchNorm batch statistics).
#define GEMM_SMEM_BYTES ((128 * 129 + 128 * 128 + 2 * 32 * 128) * 4)

template <bool PRE_BN, bool STATS>
__global__ __launch_bounds__(512) void k_gemm(const float* __restrict__ A,
                                              const float* __restrict__ W,
                                              const float* __restrict__ bias,
                                              float* __restrict__ out,
                                              float* __restrict__ sumBuf,
                                              float* __restrict__ sqBuf, int M) {
    extern __shared__ float sm[];
    float* sA = sm;                        // [128][129]
    float* sW = sm + 128 * 129;            // [128][128]
    float* sS = sW + 128 * 128;            // [32][128] col partial sums
    float* sQ = sS + 32 * 128;             // [32][128] col partial sumsq
    const int tid = threadIdx.x;
    const int bm = blockIdx.x;

#pragma unroll
    for (int i = 0; i < 32; i++) sW[i * 512 + tid] = W[i * 512 + tid];

#pragma unroll
    for (int i = 0; i < 32; i++) {
        int idx = i * 512 + tid;
        int r = idx >> 7, k = idx & 127;
        int row = bm * 128 + r;
        float v = (row < M) ? A[row * DH + k] : 0.f;
        if (PRE_BN) v = v * g_scale[k] + g_shift[k];
        sA[r * 129 + k] = v;
    }
    __syncthreads();

    const int tx = tid & 15, ty = tid >> 4;   // ty: 0..31
    const int r0 = ty * 4;
    unsigned long long acc[4][4];
#pragma unroll
    for (int i = 0; i < 4; i++)
#pragma unroll
        for (int p = 0; p < 4; p++) acc[i][p] = 0ull;

    const unsigned long long* sW2 = (const unsigned long long*)sW;

#pragma unroll 4
    for (int k = 0; k < 128; k++) {
        unsigned long long aa[4], bb[4];
#pragma unroll
        for (int i = 0; i < 4; i++) {
            float a = sA[(r0 + i) * 129 + k];
            aa[i] = pack2(a, a);
        }
#pragma unroll
        for (int p = 0; p < 4; p++) bb[p] = sW2[k * 64 + tx + 16 * p];  // cols (2tx+32p, +1)
#pragma unroll
        for (int i = 0; i < 4; i++)
#pragma unroll
            for (int p = 0; p < 4; p++) acc[i][p] = fma2(aa[i], bb[p], acc[i][p]);
    }

    const float2* bias2 = (const float2*)bias;
    float2 bsv[4];
#pragma unroll
    for (int p = 0; p < 4; p++) bsv[p] = bias2[tx + 16 * p];

    float2 ssum[4], ssq[4];
#pragma unroll
    for (int p = 0; p < 4; p++) { ssum[p] = make_float2(0.f, 0.f); ssq[p] = make_float2(0.f, 0.f); }

#pragma unroll
    for (int i = 0; i < 4; i++) {
        int row = bm * 128 + r0 + i;
        if (row >= M) continue;
        float2* orow = (float2*)(out + row * DH);
#pragma unroll
        for (int p = 0; p < 4; p++) {
            float2 v = unpack2(acc[i][p]);
            v.x = leaky(v.x + bsv[p].x);
            v.y = leaky(v.y + bsv[p].y);
            orow[tx + 16 * p] = v;
            if (STATS) {
                ssum[p].x += v.x;           ssum[p].y += v.y;
                ssq[p].x  += v.x * v.x;     ssq[p].y  += v.y * v.y;
            }
        }
    }

    if (STATS) {
#pragma unroll
        for (int p = 0; p < 4; p++) {
            int c = 2 * tx + 32 * p;
            sS[ty * 128 + c] = ssum[p].x;  sS[ty * 128 + c + 1] = ssum[p].y;
            sQ[ty * 128 + c] = ssq[p].x;   sQ[ty * 128 + c + 1] = ssq[p].y;
        }
        __syncthreads();
        if (tid < 256) {
            int c = tid & 127;
            const float* buf = (tid < 128) ? sS : sQ;
            float s = 0.f;
            for (int j = 0; j < 32; j++) {
                int r = (j + c) & 31;                    // rotation: conflict-free
                s += buf[r * 128 + c];
            }
            atomicAdd(((tid < 128) ? sumBuf : sqBuf) + c, s);
        }
    }
}

// ---------------- BN finalize ------------------------------------------------
__global__ void k_finalize(const float* __restrict__ gam, const float* __restrict__ bet,
                           const float* __restrict__ sumBuf, const float* __restrict__ sqBuf,
                           float invM) {
    int c = threadIdx.x;
    float mean = sumBuf[c] * invM;
    float var = sqBuf[c] * invM - mean * mean;
    float rstd = rsqrtf(var + BN_EPS);
    float sc = gam[c] * rstd;
    g_scale[c] = sc;
    g_shift[c] = bet[c] - mean * sc;
}

// ---------------- pooling ----------------------------------------------------
__global__ void k_gstart_init() {
    int i = threadIdx.x + blockIdx.x * blockDim.x;
    if (i <= N_GRAPHS) g_gstart[i] = N_NODES;
}
__global__ void k_gstart_mark(const int* __restrict__ batch) {
    int i = blockIdx.x * blockDim.x + threadIdx.x;
    if (i < N_NODES) {
        if (i == 0 || batch[i] != batch[i - 1]) g_gstart[batch[i]] = i;
    }
}
__global__ void k_gstart_fix() {
    for (int g = N_GRAPHS - 1; g >= 0; g--)
        if (g_gstart[g] == N_NODES) g_gstart[g] = g_gstart[g + 1];
}
__global__ __launch_bounds__(128) void k_pool(const float* __restrict__ x) {
    int g = blockIdx.x, c = threadIdx.x;
    int r0 = g_gstart[g], r1 = g_gstart[g + 1];
    float s = 0.f;
    for (int r = r0; r < r1; r++) s += x[r * DH + c];
    g_pool[g * DH + c] = s;
}

// ---------------- head -------------------------------------------------------
__global__ __launch_bounds__(128) void k_pool_stats(const float* __restrict__ bn_g,
                                                    const float* __restrict__ bn_b) {
    int c = threadIdx.x;
    float s = 0.f, q = 0.f;
    for (int g = 0; g < N_GRAPHS; g++) {
        float v = g_pool[g * DH + c];
        s += v; q += v * v;
    }
    float mean = s / (float)N_GRAPHS;
    float var = q / (float)N_GRAPHS - mean * mean;
    float rstd = rsqrtf(var + BN_EPS);
    float sc = bn_g[c] * rstd;
    g_scale[c] = sc;
    g_shift[c] = bn_b[c] - mean * sc;
    if (c < DL) { g_fsum[c] = 0.f; g_fsq[c] = 0.f; }
}

__global__ __launch_bounds__(64) void k_head2(const float* __restrict__ feats,
                                              const float* __restrict__ fcW,
                                              const float* __restrict__ fcb,
                                              const float* __restrict__ cW1,
                                              const float* __restrict__ cb1,
                                              const float* __restrict__ cW2,
                                              const float* __restrict__ cb2,
                                              const float* __restrict__ fW1,
                                              const float* __restrict__ fb1) {
    __shared__ float cat[DL + 8];
    __shared__ float t8[8];
    int g = blockIdx.x, j = threadIdx.x;
    if (j < 8) {
        float s = cb1[j];
        for (int i = 0; i < 7; i++) s += feats[g * 7 + i] * cW1[i * 8 + j];
        t8[j] = fmaxf(s, 0.f);
    }
    __syncthreads();
    if (j < 8) {
        float s = cb2[j];
        for (int i = 0; i < 8; i++) s += t8[i] * cW2[i * 8 + j];
        cat[DL + j] = s;
    }
    float o = fcb[j];
    for (int k = 0; k < DH; k++) {
        float a = g_pool[g * DH + k] * g_scale[k] + g_shift[k];
        o += a * fcW[k * DL + j];
    }
    cat[j] = o;
    __syncthreads();
    float s = fb1[j];
    for (int k = 0; k < DL + 8; k++) s += cat[k] * fW1[k * DL + j];
    float v = leaky(s);
    g_f1[g * DL + j] = v;
    atomicAdd(&g_fsum[j], v);
    atomicAdd(&g_fsq[j], v * v);
}

__global__ __launch_bounds__(64) void k_head3(const float* __restrict__ f_g,
                                              const float* __restrict__ f_b) {
    int j = threadIdx.x;
    float mean = g_fsum[j] / (float)N_GRAPHS;
    float var = g_fsq[j] / (float)N_GRAPHS - mean * mean;
    float rstd = rsqrtf(var + BN_EPS);
    float sc = f_g[j] * rstd;
    g_fscale[j] = sc;
    g_fshift[j] = f_b[j] - mean * sc;
}

__global__ __launch_bounds__(64) void k_head4(const float* __restrict__ fW2,
                                              const float* __restrict__ fb2,
                                              float* __restrict__ out) {
    int g = blockIdx.x, j = threadIdx.x;
    float s = fb2[j];
    for (int k = 0; k < DL; k++) {
        float a = g_f1[g * DL + k] * g_fscale[k] + g_fshift[k];
        s += a * fW2[k * DL + j];
    }
    out[g * DL + j] = s;
}

// ---------------- launch -----------------------------------------------------
extern "C" void kernel_launch(void* const* d_in, const int* in_sizes, int n_in,
                              void* d_out, int out_size) {
    (void)in_sizes; (void)n_in; (void)out_size;
    const float* x      = (const float*)d_in[0];
    const int*   ei     = (const int*)  d_in[1];
    const int*   batch  = (const int*)  d_in[2];
    const float* feats  = (const float*)d_in[3];
    const float* convW1 = (const float*)d_in[4];
    const float* convb1 = (const float*)d_in[5];
    const float* convg1 = (const float*)d_in[6];
    const float* convbb1= (const float*)d_in[7];
    const float* convW2 = (const float*)d_in[8];
    const float* convb2 = (const float*)d_in[9];
    const float* bn_g   = (const float*)d_in[10];
    const float* bn_b   = (const float*)d_in[11];
    const float* fcW    = (const float*)d_in[12];
    const float* fcb    = (const float*)d_in[13];
    const float* cW1    = (const float*)d_in[14];
    const float* cb1    = (const float*)d_in[15];
    const float* cW2    = (const float*)d_in[16];
    const float* cb2    = (const float*)d_in[17];
    const float* fW1    = (const float*)d_in[18];
    const float* fb1    = (const float*)d_in[19];
    const float* f_g    = (const float*)d_in[20];
    const float* f_b    = (const float*)d_in[21];
    const float* fW2    = (const float*)d_in[22];
    const float* fb2    = (const float*)d_in[23];
    float* out = (float*)d_out;

    static bool attr_done = false;
    if (!attr_done) {
        cudaFuncSetAttribute(k_gemm<false, true>,
                             cudaFuncAttributeMaxDynamicSharedMemorySize, GEMM_SMEM_BYTES);
        cudaFuncSetAttribute(k_gemm<true, false>,
                             cudaFuncAttributeMaxDynamicSharedMemorySize, GEMM_SMEM_BYTES);
        attr_done = true;
    }

    float *dxa, *dxb, *dh0, *dt, *dsum, *dsq;
    cudaGetSymbolAddress((void**)&dxa, g_xa);
    cudaGetSymbolAddress((void**)&dxb, g_xb);
    cudaGetSymbolAddress((void**)&dh0, g_h0);
    cudaGetSymbolAddress((void**)&dt,  g_t);
    cudaGetSymbolAddress((void**)&dsum, g_sum);
    cudaGetSymbolAddress((void**)&dsq,  g_sq);

    // CSR build (rebuilt every launch: deterministic same-work)
    k_zero_cnt<<<(N_NODES + 255) / 256, 256>>>();
    k_hist<<<(N_EDGES + 255) / 256, 256>>>(ei);
    k_scan<<<1, 1024>>>();
    k_fill<<<(N_EDGES + 255) / 256, 256>>>(ei);

    const int AGG_GRID  = (N_NODES * 32 + 255) / 256;
    const int GEMM_GRID = (N_NODES + 127) / 128;
    const float invM = 1.0f / (float)N_NODES;

    float* xouts[3] = {dxa, dxb, dxa};
    const float* xin = x;

    for (int l = 0; l < N_LAYERS; l++) {
        k_agg<<<AGG_GRID, 256>>>(xin);
        k_gemm<false, true><<<GEMM_GRID, 512, GEMM_SMEM_BYTES>>>(
            dh0, convW1 + l * DH * DH, convb1 + l * DH, dt,
            dsum + l * DH, dsq + l * DH, N_NODES);
        k_finalize<<<1, 128>>>(convg1 + l * DH, convbb1 + l * DH,
                               dsum + l * DH, dsq + l * DH, invM);
        k_gemm<true, false><<<GEMM_GRID, 512, GEMM_SMEM_BYTES>>>(
            dt, convW2 + l * DH * DH, convb2 + l * DH, xouts[l],
            nullptr, nullptr, N_NODES);
        xin = xouts[l];
    }

    // pooling via sorted-batch ranges (atomic-free)
    k_gstart_init<<<3, 256>>>();
    k_gstart_mark<<<(N_NODES + 255) / 256, 256>>>(batch);
    k_gstart_fix<<<1, 1>>>();
    k_pool<<<N_GRAPHS, 128>>>(xin);

    // head
    k_pool_stats<<<1, 128>>>(bn_g, bn_b);
    k_head2<<<N_GRAPHS, 64>>>(feats, fcW, fcb, cW1, cb1, cW2, cb2, fW1, fb1);
    k_head3<<<1, 64>>>(f_g, f_b);
    k_head4<<<N_GRAPHS, 64>>>(fW2, fb2, out);
}